// round 16
// baseline (speedup 1.0000x reference)
#include <cuda_runtime.h>
#include <math.h>
#include <stdint.h>

// Problem constants (fixed by the seeded reference):
//   m=8, nc=1024, nt=512, dim=2, PPU=64 -> grid 129x129 per batch.
#define M_B   8
#define NC    1024
#define NT    512
#define AX    129
#define NG    (AX * AX)            // 16641
#define HALF  64
#define INV_PPU (1.0f / 64.0f)
#define X_TOTAL (M_B * NG * 2)
#define TOT_Z (M_B * NG * 3)       // 399384
#define PHALF TOT_Z                // floats per K-split partial

#define NSPL  4                    // K-splits
#define KS    256                  // contexts per split
#define NTHR  288                  // 9 warps: 8 main (4 ig x 2 jg) + 1 edge
#define JTW   16                   // j columns per CTA
#define NJT   9                    // 9 x 16 = 144 >= 129 (jt==8 is the slim j=128 tile)

// Dynamic smem: wyy [256 c][3 ch][16 j] floats (49152 B) then cxk [256]
#define WYY_BYTES (KS * 192)
#define CXK_OFF   WYY_BYTES
#define SMEM_M    (WYY_BYTES + KS * 4)   // 50176

// K-split partial scratch in final z layout: [ks 4][b][i][j][ch]
__device__ __align__(16) float g_part[NSPL * PHALF];   // 6.4 MB
// per-(jt,b) arrival counters; zero-init, self-resetting each launch
__device__ unsigned int g_cnt[NJT * M_B];

__device__ __forceinline__ float ex2f(float x) {
    float r; asm("ex2.approx.f32 %0, %1;" : "=f"(r) : "f"(x)); return r;
}
__device__ __forceinline__ float soft_k(float p) {
    // weight = 2^(-((d*k)^2)), k = sqrt(0.5*log2(e)) / (1e-5 + softplus(p))
    float ls = 1e-5f + log1pf(expf(p));
    return sqrtf(0.5f * 1.44269504088896341f) / ls;
}
__device__ __forceinline__ uint32_t sm32(const void* p) {
    uint32_t a;
    asm("{ .reg .u64 t; cvta.to.shared.u64 t, %1; cvt.u32.u64 %0, t; }" : "=r"(a) : "l"(p));
    return a;
}
#define FMA2(acc, a, b) \
    asm("fma.rn.f32x2 %0, %1, %2, %0;" : "+l"(acc) : "l"(a), "l"(b))
#define PACK2(d, w) \
    asm("mov.b64 %0, {%1, %1};" : "=l"(d) : "f"(w))

extern __shared__ char dynsm[];

// ---------------- Main kernel: fused setconv + last-CTA combine ----------------
__global__ void __launch_bounds__(NTHR, 2)
main_kernel(const float* __restrict__ xc, const float* __restrict__ yc,
            const float* __restrict__ xt, const float* __restrict__ lsp,
            float* __restrict__ out) {
    const int ks = blockIdx.x & 3;          // K split
    const int jt = blockIdx.x >> 2;         // 0..8
    const int b  = blockIdx.y;
    const int tid = threadIdx.x;
    const int w = tid >> 5, l = tid & 31;
    const uint32_t smb = sm32(dynsm);
    float* wyyf  = (float*)dynsm;
    float* s_cxk = (float*)(dynsm + CXK_OFF);

    __shared__ float s_red[4][9];
    __shared__ float2 s_mid;
    __shared__ unsigned int s_old;

    // ---- per-CTA min/max over concat(xc, xt) ----
    float mn0 = 1e30f, mx0 = -1e30f, mn1 = 1e30f, mx1 = -1e30f;
    for (int idx = tid; idx < NC + NT; idx += NTHR) {
        const float2 p = (idx < NC)
            ? *(const float2*)(xc + (size_t)(b * NC + idx) * 2)
            : *(const float2*)(xt + (size_t)(b * NT + idx - NC) * 2);
        mn0 = fminf(mn0, p.x); mx0 = fmaxf(mx0, p.x);
        mn1 = fminf(mn1, p.y); mx1 = fmaxf(mx1, p.y);
    }
    for (int o = 16; o; o >>= 1) {
        mn0 = fminf(mn0, __shfl_xor_sync(~0u, mn0, o));
        mx0 = fmaxf(mx0, __shfl_xor_sync(~0u, mx0, o));
        mn1 = fminf(mn1, __shfl_xor_sync(~0u, mn1, o));
        mx1 = fmaxf(mx1, __shfl_xor_sync(~0u, mx1, o));
    }
    if (l == 0) { s_red[0][w] = mn0; s_red[1][w] = mx0; s_red[2][w] = mn1; s_red[3][w] = mx1; }
    __syncthreads();
    if (tid == 0) {
        float a = s_red[0][0], bb = s_red[1][0], c = s_red[2][0], d = s_red[3][0];
        #pragma unroll
        for (int k = 1; k < 9; k++) {
            a = fminf(a, s_red[0][k]); bb = fmaxf(bb, s_red[1][k]);
            c = fminf(c, s_red[2][k]); d = fmaxf(d, s_red[3][k]);
        }
        s_mid = make_float2(0.5f * (a + bb), 0.5f * (c + d));
    }
    const float k0 = soft_k(lsp[0]);
    const float k1 = soft_k(lsp[1]);
    __syncthreads();
    const float2 mid = s_mid;

    // ---- prologue: cxk + wyy tables (wyy pre-multiplied by ex2(-cx^2)) ----
    const int c0 = ks * KS;
    for (int c = tid; c < KS; c += NTHR)
        s_cxk[c] = xc[(size_t)(b * NC + c0 + c) * 2] * k0;
    for (int idx = tid; idx < KS * JTW; idx += NTHR) {
        const int c = idx >> 4, jj = idx & 15;
        const int j = jt * JTW + jj;
        const float2 vxy = *(const float2*)(xc + (size_t)(b * NC + c0 + c) * 2);
        const float2 yv  = *(const float2*)(yc + (size_t)(b * NC + c0 + c) * 2);
        const float cx = vxy.x * k0;
        const float fx = ex2f(-(cx * cx));
        float wv = 0.0f;
        if (j <= 128) {
            const float d = (mid.y + (float)(j - HALF) * INV_PPU - vxy.y) * k1;
            wv = ex2f(-(d * d));
        }
        wv *= fx;
        float* dst = wyyf + c * 48 + jj;
        dst[0] = wv * yv.x; dst[16] = wv * yv.y; dst[32] = wv;
    }
    __syncthreads();

    if (w < 8) {
        const int ig = w & 3, jg = w >> 2;
        const int i = ig * 32 + l;
        const float axk = (mid.x + (float)(i - HALF) * INV_PPU) * k0;
        const float a2 = axk + axk;
        const float ai = -(axk * axk);

        if (jt == 8) {
            // ---- slim tile: only j = 128 is real; jg==0 warps do the column ----
            if (jg == 0) {
                float e0 = 0.f, e1 = 0.f, e2 = 0.f;
                #pragma unroll 8
                for (int c4 = 0; c4 < KS / 4; c4++) {
                    const float4 cx4 = *(const float4*)(s_cxk + c4 * 4);
                    #pragma unroll
                    for (int u = 0; u < 4; u++) {
                        const int c = c4 * 4 + u;
                        const float cx = (u == 0) ? cx4.x : (u == 1) ? cx4.y
                                       : (u == 2) ? cx4.z : cx4.w;
                        const float wxv = ex2f(fmaf(a2, cx, ai));
                        e0 = fmaf(wxv, wyyf[c * 48],      e0);
                        e1 = fmaf(wxv, wyyf[c * 48 + 16], e1);
                        e2 = fmaf(wxv, wyyf[c * 48 + 32], e2);
                    }
                }
                float* pp = g_part + (size_t)ks * PHALF
                          + ((size_t)(b * NG) + (size_t)i * AX + 128) * 3;
                pp[0] = e0; pp[1] = e1; pp[2] = e2;
            }
        } else {
            // ---- full tile: i = ig*32 + lane, 8 j's (jg) x 3 ch ----
            const uint32_t wya = smb + (uint32_t)jg * 32;
            unsigned long long acc[12];    // [ch 0..2][pair 0..3]
            #pragma unroll
            for (int q = 0; q < 12; q++) acc[q] = 0;

            #pragma unroll 4
            for (int c4 = 0; c4 < KS / 4; c4++) {
                const float4 cx4 = *(const float4*)(s_cxk + c4 * 4);
                const uint32_t wb = wya + (uint32_t)c4 * 768;
                #pragma unroll
                for (int u = 0; u < 4; u++) {
                    const float cx = (u == 0) ? cx4.x : (u == 1) ? cx4.y
                                   : (u == 2) ? cx4.z : cx4.w;
                    const float wxv = ex2f(fmaf(a2, cx, ai));
                    unsigned long long wxp; PACK2(wxp, wxv);
                    unsigned long long q0, q1, q2, q3, q4, q5, q6, q7, q8, q9, qa, qb;
                    const uint32_t ub = wb + (uint32_t)u * 192;
                    asm("ld.shared.v2.u64 {%0,%1}, [%2];"     : "=l"(q0), "=l"(q1) : "r"(ub));
                    asm("ld.shared.v2.u64 {%0,%1}, [%2+16];"  : "=l"(q2), "=l"(q3) : "r"(ub));
                    asm("ld.shared.v2.u64 {%0,%1}, [%2+64];"  : "=l"(q4), "=l"(q5) : "r"(ub));
                    asm("ld.shared.v2.u64 {%0,%1}, [%2+80];"  : "=l"(q6), "=l"(q7) : "r"(ub));
                    asm("ld.shared.v2.u64 {%0,%1}, [%2+128];" : "=l"(q8), "=l"(q9) : "r"(ub));
                    asm("ld.shared.v2.u64 {%0,%1}, [%2+144];" : "=l"(qa), "=l"(qb) : "r"(ub));
                    FMA2(acc[0], wxp, q0); FMA2(acc[1], wxp, q1);
                    FMA2(acc[2], wxp, q2); FMA2(acc[3], wxp, q3);
                    FMA2(acc[4], wxp, q4); FMA2(acc[5], wxp, q5);
                    FMA2(acc[6], wxp, q6); FMA2(acc[7], wxp, q7);
                    FMA2(acc[8], wxp, q8); FMA2(acc[9], wxp, q9);
                    FMA2(acc[10], wxp, qa); FMA2(acc[11], wxp, qb);
                }
            }

            // guarded stores, final-z layout
            const int j0 = jt * JTW + jg * 8;
            union { unsigned long long u; float f[2]; } v;
            #pragma unroll
            for (int jj = 0; jj < 8; jj++) {
                const int j = j0 + jj;
                if (j < AX) {
                    float* pp = g_part + (size_t)ks * PHALF
                              + ((size_t)(b * NG) + (size_t)i * AX + j) * 3;
                    #pragma unroll
                    for (int ch = 0; ch < 3; ch++) {
                        v.u = acc[ch * 4 + (jj >> 1)];
                        pp[ch] = v.f[jj & 1];
                    }
                }
            }
        }
    } else if (l < 16) {
        // ---- edge warp: i = 128 row, up to 16 j's (one per lane) ----
        const int j = jt * JTW + l;
        if (j < AX) {
            const float axe = (mid.x + (float)(128 - HALF) * INV_PPU) * k0;
            const float a2e = axe + axe;
            const float aie = -(axe * axe);
            float e0 = 0.f, e1 = 0.f, e2 = 0.f;
            #pragma unroll 4
            for (int c = 0; c < KS; c++) {
                const float cx = s_cxk[c];
                const float wxv = ex2f(fmaf(a2e, cx, aie));
                e0 = fmaf(wxv, wyyf[c * 48 + l],      e0);
                e1 = fmaf(wxv, wyyf[c * 48 + 16 + l], e1);
                e2 = fmaf(wxv, wyyf[c * 48 + 32 + l], e2);
            }
            float* pp = g_part + (size_t)ks * PHALF
                      + ((size_t)(b * NG) + (size_t)128 * AX + j) * 3;
            pp[0] = e0; pp[1] = e1; pp[2] = e2;
        }
    }

    // ---- x_grid from ks == 0 CTAs (bit-exact forms) ----
    if (ks == 0) {
        for (int idx = tid; idx < AX * JTW; idx += NTHR) {
            const int i = idx >> 4, jj = idx & 15;
            const int j = jt * JTW + jj;
            if (j < AX) {
                float2* xg = (float2*)out + (size_t)(b * NG) + (size_t)i * AX + j;
                *xg = make_float2(mid.x + (float)(i - HALF) * INV_PPU,
                                  mid.y + (float)(j - HALF) * INV_PPU);
            }
        }
    }

    // ---- last-CTA-per-tile combine: z = p0+p1+p2+p3 for this (jt, b) region ----
    __threadfence();
    __syncthreads();
    if (tid == 0) s_old = atomicAdd(&g_cnt[jt * M_B + b], 1u);
    __syncthreads();
    if (s_old == 3u) {
        __threadfence();   // make other CTAs' partial stores visible
        const float* p1 = g_part + (size_t)PHALF;
        const float* p2 = g_part + 2 * (size_t)PHALF;
        const float* p3 = g_part + 3 * (size_t)PHALF;
        if (jt < 8) {
            const int col = tid % 48;                 // 48 floats per i-row (16 j x 3 ch)
            #pragma unroll 4
            for (int i = tid / 48; i < AX; i += 6) {
                const size_t off = (size_t)(b * NG + i * AX) * 3 + (size_t)(jt * 48 + col);
                const float r = (g_part[off] + p1[off]) + (p2[off] + p3[off]);
                out[(size_t)X_TOTAL + off] = r;
            }
        } else {
            #pragma unroll 4
            for (int idx = tid; idx < AX * 3; idx += NTHR) {
                const int i = idx / 3, ch = idx - i * 3;
                const size_t off = (size_t)(b * NG + i * AX + 128) * 3 + ch;
                const float r = (g_part[off] + p1[off]) + (p2[off] + p3[off]);
                out[(size_t)X_TOTAL + off] = r;
            }
        }
        __syncthreads();
        if (tid == 0) g_cnt[jt * M_B + b] = 0u;   // self-reset for next launch/replay
    }
}

extern "C" void kernel_launch(void* const* d_in, const int* in_sizes, int n_in,
                              void* d_out, int out_size) {
    const float* xc  = (const float*)d_in[0];
    const float* yc  = (const float*)d_in[1];
    const float* xt  = (const float*)d_in[2];
    const float* lsp = (const float*)d_in[3];
    float* out = (float*)d_out;

    cudaFuncSetAttribute(main_kernel, cudaFuncAttributeMaxDynamicSharedMemorySize, SMEM_M);
    main_kernel<<<dim3(NSPL * NJT, M_B), NTHR, SMEM_M>>>(xc, yc, xt, lsp, out);
}

// round 17
// speedup vs baseline: 1.1950x; 1.1950x over previous
#include <cuda_runtime.h>
#include <math.h>
#include <stdint.h>

// Problem constants (fixed by the seeded reference):
//   m=8, nc=1024, nt=512, dim=2, PPU=64 -> grid 129x129 per batch.
#define M_B   8
#define NC    1024
#define NT    512
#define AX    129
#define NG    (AX * AX)            // 16641
#define HALF  64
#define INV_PPU (1.0f / 64.0f)
#define X_TOTAL (M_B * NG * 2)
#define TOT_Z (M_B * NG * 3)       // 399384
#define PHALF TOT_Z                // floats per K-split partial

#define NSPL  4                    // K-splits
#define KS    256                  // contexts per split
#define NTHR  544                  // 17 warps: 16 main (4 ig x 4 jg) + 1 edge
#define JTW   16                   // j columns per CTA
#define NJT   9                    // 9 x 16 = 144 >= 129 (jt==8 is the slim j=128 tile)

// Dynamic smem: wyy [256 c][4 jg][3 ch][2 pair][2 e] floats (49152 B) then cxk [256]
#define WYY_BYTES (KS * 192)
#define CXK_OFF   WYY_BYTES
#define SMEM_M    (WYY_BYTES + KS * 4)   // 50176

// K-split partial scratch in final z layout: [ks 4][b][i][j][ch]
__device__ __align__(16) float g_part[NSPL * PHALF];   // 6.4 MB

__device__ __forceinline__ float ex2f(float x) {
    float r; asm("ex2.approx.f32 %0, %1;" : "=f"(r) : "f"(x)); return r;
}
__device__ __forceinline__ float soft_k(float p) {
    // weight = 2^(-((d*k)^2)), k = sqrt(0.5*log2(e)) / (1e-5 + softplus(p))
    float ls = 1e-5f + log1pf(expf(p));
    return sqrtf(0.5f * 1.44269504088896341f) / ls;
}
__device__ __forceinline__ uint32_t sm32(const void* p) {
    uint32_t a;
    asm("{ .reg .u64 t; cvta.to.shared.u64 t, %1; cvt.u32.u64 %0, t; }" : "=r"(a) : "l"(p));
    return a;
}
#define FMA2(acc, a, b) \
    asm("fma.rn.f32x2 %0, %1, %2, %0;" : "+l"(acc) : "l"(a), "l"(b))
#define PACK2(d, w) \
    asm("mov.b64 %0, {%1, %1};" : "=l"(d) : "f"(w))

extern __shared__ char dynsm[];

// ---------------- Main kernel: fused setconv with K-split partials ----------------
__global__ void __launch_bounds__(NTHR, 2)
main_kernel(const float* __restrict__ xc, const float* __restrict__ yc,
            const float* __restrict__ xt, const float* __restrict__ lsp,
            float* __restrict__ out) {
    const int ks = blockIdx.x & 3;          // K split
    const int jt = blockIdx.x >> 2;         // 0..8
    const int b  = blockIdx.y;
    const int tid = threadIdx.x;
    const int w = tid >> 5, l = tid & 31;
    const uint32_t smb = sm32(dynsm);
    float* wyyf  = (float*)dynsm;
    float* s_cxk = (float*)(dynsm + CXK_OFF);

    __shared__ float s_red[4][17];
    __shared__ float2 s_mid;

    // ---- per-CTA min/max over concat(xc, xt) ----
    float mn0 = 1e30f, mx0 = -1e30f, mn1 = 1e30f, mx1 = -1e30f;
    for (int idx = tid; idx < NC + NT; idx += NTHR) {
        const float2 p = (idx < NC)
            ? *(const float2*)(xc + (size_t)(b * NC + idx) * 2)
            : *(const float2*)(xt + (size_t)(b * NT + idx - NC) * 2);
        mn0 = fminf(mn0, p.x); mx0 = fmaxf(mx0, p.x);
        mn1 = fminf(mn1, p.y); mx1 = fmaxf(mx1, p.y);
    }
    for (int o = 16; o; o >>= 1) {
        mn0 = fminf(mn0, __shfl_xor_sync(~0u, mn0, o));
        mx0 = fmaxf(mx0, __shfl_xor_sync(~0u, mx0, o));
        mn1 = fminf(mn1, __shfl_xor_sync(~0u, mn1, o));
        mx1 = fmaxf(mx1, __shfl_xor_sync(~0u, mx1, o));
    }
    if (l == 0) { s_red[0][w] = mn0; s_red[1][w] = mx0; s_red[2][w] = mn1; s_red[3][w] = mx1; }
    __syncthreads();
    if (tid == 0) {
        float a = s_red[0][0], bb = s_red[1][0], c = s_red[2][0], d = s_red[3][0];
        #pragma unroll
        for (int k = 1; k < 17; k++) {
            a = fminf(a, s_red[0][k]); bb = fmaxf(bb, s_red[1][k]);
            c = fminf(c, s_red[2][k]); d = fmaxf(d, s_red[3][k]);
        }
        s_mid = make_float2(0.5f * (a + bb), 0.5f * (c + d));
    }
    const float k0 = soft_k(lsp[0]);
    const float k1 = soft_k(lsp[1]);
    __syncthreads();
    const float2 mid = s_mid;

    // ---- prologue: cxk + wyy tables (wyy pre-multiplied by ex2(-cx^2)) ----
    const int c0 = ks * KS;
    for (int c = tid; c < KS; c += NTHR)
        s_cxk[c] = xc[(size_t)(b * NC + c0 + c) * 2] * k0;
    for (int idx = tid; idx < KS * JTW; idx += NTHR) {
        const int c = idx >> 4, jj = idx & 15;
        const int j = jt * JTW + jj;
        const float2 vxy = *(const float2*)(xc + (size_t)(b * NC + c0 + c) * 2);
        const float2 yv  = *(const float2*)(yc + (size_t)(b * NC + c0 + c) * 2);
        const float cx = vxy.x * k0;
        const float fx = ex2f(-(cx * cx));
        float wv = 0.0f;
        if (j <= 128) {
            const float d = (mid.y + (float)(j - HALF) * INV_PPU - vxy.y) * k1;
            wv = ex2f(-(d * d));
        }
        wv *= fx;
        // layout: [c][jg][ch][pair][e]
        float* dst = wyyf + c * 48 + (jj >> 2) * 12 + ((jj >> 1) & 1) * 2 + (jj & 1);
        dst[0] = wv * yv.x; dst[4] = wv * yv.y; dst[8] = wv;
    }
    __syncthreads();

    if (w < 16) {
        const int ig = w & 3, jg = w >> 2;
        const int i = ig * 32 + l;
        const float axk = (mid.x + (float)(i - HALF) * INV_PPU) * k0;
        const float a2 = axk + axk;
        const float ai = -(axk * axk);

        if (jt == 8) {
            // ---- slim tile: only j = 128 is real; jg==0 warps compute it ----
            if (jg == 0) {
                float e0 = 0.f, e1 = 0.f, e2 = 0.f;
                #pragma unroll 8
                for (int c4 = 0; c4 < KS / 4; c4++) {
                    const float4 cx4 = *(const float4*)(s_cxk + c4 * 4);
                    #pragma unroll
                    for (int u = 0; u < 4; u++) {
                        const int c = c4 * 4 + u;
                        const float cx = (u == 0) ? cx4.x : (u == 1) ? cx4.y
                                       : (u == 2) ? cx4.z : cx4.w;
                        const float wxv = ex2f(fmaf(a2, cx, ai));
                        e0 = fmaf(wxv, wyyf[c * 48],     e0);
                        e1 = fmaf(wxv, wyyf[c * 48 + 4], e1);
                        e2 = fmaf(wxv, wyyf[c * 48 + 8], e2);
                    }
                }
                float* pp = g_part + (size_t)ks * PHALF
                          + ((size_t)(b * NG) + (size_t)i * AX + 128) * 3;
                pp[0] = e0; pp[1] = e1; pp[2] = e2;
            }
        } else {
            // ---- full tile: i = ig*32 + lane, 4 j's (jg) x 3 ch ----
            const uint32_t wya = smb + (uint32_t)jg * 48;
            unsigned long long acc[6];     // [ch 0..2][pair 0..1]
            #pragma unroll
            for (int q = 0; q < 6; q++) acc[q] = 0;

            #pragma unroll 4
            for (int c4 = 0; c4 < KS / 4; c4++) {
                const float4 cx4 = *(const float4*)(s_cxk + c4 * 4);
                const uint32_t wb = wya + (uint32_t)c4 * 768;
                #pragma unroll
                for (int u = 0; u < 4; u++) {
                    const float cx = (u == 0) ? cx4.x : (u == 1) ? cx4.y
                                   : (u == 2) ? cx4.z : cx4.w;
                    const float wxv = ex2f(fmaf(a2, cx, ai));
                    unsigned long long wxp; PACK2(wxp, wxv);
                    unsigned long long q0, q1, q2, q3, q4, q5;
                    const uint32_t ub = wb + (uint32_t)u * 192;
                    asm("ld.shared.v2.u64 {%0,%1}, [%2];"    : "=l"(q0), "=l"(q1) : "r"(ub));
                    asm("ld.shared.v2.u64 {%0,%1}, [%2+16];" : "=l"(q2), "=l"(q3) : "r"(ub));
                    asm("ld.shared.v2.u64 {%0,%1}, [%2+32];" : "=l"(q4), "=l"(q5) : "r"(ub));
                    FMA2(acc[0], wxp, q0); FMA2(acc[1], wxp, q1);
                    FMA2(acc[2], wxp, q2); FMA2(acc[3], wxp, q3);
                    FMA2(acc[4], wxp, q4); FMA2(acc[5], wxp, q5);
                }
            }

            // guarded stores, final-z layout
            const int j0 = jt * JTW + jg * 4;
            union { unsigned long long u; float f[2]; } v;
            #pragma unroll
            for (int jj = 0; jj < 4; jj++) {
                const int j = j0 + jj;
                if (j < AX) {
                    float* pp = g_part + (size_t)ks * PHALF
                              + ((size_t)(b * NG) + (size_t)i * AX + j) * 3;
                    #pragma unroll
                    for (int ch = 0; ch < 3; ch++) {
                        v.u = acc[ch * 2 + (jj >> 1)];
                        pp[ch] = v.f[jj & 1];
                    }
                }
            }
        }
    } else if (l < 16) {
        // ---- edge warp: i = 128 row, up to 16 j's (one per lane) ----
        const int j = jt * JTW + l;
        if (j < AX) {
            const float axe = (mid.x + (float)(128 - HALF) * INV_PPU) * k0;
            const float a2e = axe + axe;
            const float aie = -(axe * axe);
            const int fo = (l >> 2) * 12 + ((l >> 1) & 1) * 2 + (l & 1);
            float e0 = 0.f, e1 = 0.f, e2 = 0.f;
            #pragma unroll 4
            for (int c = 0; c < KS; c++) {
                const float cx = s_cxk[c];
                const float wxv = ex2f(fmaf(a2e, cx, aie));
                e0 = fmaf(wxv, wyyf[c * 48 + fo],     e0);
                e1 = fmaf(wxv, wyyf[c * 48 + fo + 4], e1);
                e2 = fmaf(wxv, wyyf[c * 48 + fo + 8], e2);
            }
            float* pp = g_part + (size_t)ks * PHALF
                      + ((size_t)(b * NG) + (size_t)128 * AX + j) * 3;
            pp[0] = e0; pp[1] = e1; pp[2] = e2;
        }
    }

    // ---- x_grid from ks == 0 CTAs (bit-exact forms) ----
    if (ks == 0) {
        for (int idx = tid; idx < AX * JTW; idx += NTHR) {
            const int i = idx >> 4, jj = idx & 15;
            const int j = jt * JTW + jj;
            if (j < AX) {
                float2* xg = (float2*)out + (size_t)(b * NG) + (size_t)i * AX + j;
                *xg = make_float2(mid.x + (float)(i - HALF) * INV_PPU,
                                  mid.y + (float)(j - HALF) * INV_PPU);
            }
        }
    }
}

// ---------------- Combine kernel: out_z = p0+p1+p2+p3 (1 float4 / thread) ----------------
__global__ void __launch_bounds__(256) combine_kernel(float* __restrict__ out) {
    const int t = blockIdx.x * 256 + threadIdx.x;
    if (t < TOT_Z / 4) {
        const float4 a0 = __ldg((const float4*)g_part + t);
        const float4 a1 = __ldg((const float4*)(g_part + PHALF) + t);
        const float4 a2 = __ldg((const float4*)(g_part + 2 * (size_t)PHALF) + t);
        const float4 a3 = __ldg((const float4*)(g_part + 3 * (size_t)PHALF) + t);
        float4 r;
        r.x = (a0.x + a1.x) + (a2.x + a3.x);
        r.y = (a0.y + a1.y) + (a2.y + a3.y);
        r.z = (a0.z + a1.z) + (a2.z + a3.z);
        r.w = (a0.w + a1.w) + (a2.w + a3.w);
        ((float4*)(out + X_TOTAL))[t] = r;
    }
}

extern "C" void kernel_launch(void* const* d_in, const int* in_sizes, int n_in,
                              void* d_out, int out_size) {
    const float* xc  = (const float*)d_in[0];
    const float* yc  = (const float*)d_in[1];
    const float* xt  = (const float*)d_in[2];
    const float* lsp = (const float*)d_in[3];
    float* out = (float*)d_out;

    cudaFuncSetAttribute(main_kernel, cudaFuncAttributeMaxDynamicSharedMemorySize, SMEM_M);
    main_kernel<<<dim3(NSPL * NJT, M_B), NTHR, SMEM_M>>>(xc, yc, xt, lsp, out);
    combine_kernel<<<(TOT_Z / 4 + 255) / 256, 256>>>(out);
}